// round 16
// baseline (speedup 1.0000x reference)
#include <cuda_runtime.h>
#include <cstdint>

#define H 2048
#define B 16
#define S 256
#define V 32000
#define NBLK 128
#define NTHR 512
#define PPAD 17

__device__ float g_E[2][H * B];    // tf32-rounded exp(y_t - shift_t), dbl buffered
__device__ float g_shift[2][B];    // shift_t[b] = y_t[0,b] (block 0, row 0)
__device__ unsigned g_flag[NBLK];  // monotonic epochs: done step t => base+t+1
__device__ float g_ip[(size_t)S * H * B];  // pre-gathered ip[t][h][b] (33.5MB)
__device__ int g_head[V];                  // column -> chain head ((t<<4)|b), -1 none
__device__ int g_next[S * B];              // chain links

__device__ __forceinline__ unsigned cvt_tf32(float f) {
    unsigned r; asm("cvt.rna.tf32.f32 %0, %1;" : "=r"(r) : "f"(f)); return r;
}
__device__ __forceinline__ void mma_tf32(float* d, const unsigned* a,
                                         const unsigned* b, const float* c) {
    asm("mma.sync.aligned.m16n8k8.row.col.f32.tf32.tf32.f32 "
        "{%0,%1,%2,%3}, {%4,%5,%6,%7}, {%8,%9}, {%10,%11,%12,%13};"
        : "=f"(d[0]), "=f"(d[1]), "=f"(d[2]), "=f"(d[3])
        : "r"(a[0]), "r"(a[1]), "r"(a[2]), "r"(a[3]),
          "r"(b[0]), "r"(b[1]),
          "f"(c[0]), "f"(c[1]), "f"(c[2]), "f"(c[3]));
}
__device__ __forceinline__ void atom_rel_exch(unsigned* p, unsigned v) {
    unsigned old;
    asm volatile("atom.release.gpu.global.exch.b32 %0, [%1], %2;"
                 : "=r"(old) : "l"(p), "r"(v) : "memory");
}

// ---------------------------------------------------------------------------
// prep: head = -1, g_ip = 0
// ---------------------------------------------------------------------------
__global__ void prep_kernel() {
    const size_t gtid = (size_t)blockIdx.x * blockDim.x + threadIdx.x;
    const size_t stride = (size_t)gridDim.x * blockDim.x;
    for (size_t i = gtid; i < V; i += stride) g_head[i] = -1;
    float4* p4 = reinterpret_cast<float4*>(g_ip);
    const size_t n4 = (size_t)S * H * B / 4;
    float4 z = make_float4(0.f, 0.f, 0.f, 0.f);
    for (size_t i = gtid; i < n4; i += stride) p4[i] = z;
}

// ---------------------------------------------------------------------------
// build chain map: for (t,b): id = ids[b, S-1-t]; push (t<<4|b) onto head[id]
// ---------------------------------------------------------------------------
__global__ void build_kernel(const int* __restrict__ ids) {
    int i = blockIdx.x * blockDim.x + threadIdx.x;  // 0..S*B
    if (i < S * B) {
        int t = i >> 4, b = i & 15;
        int id = ids[b * S + (S - 1 - t)];
        if (id >= 0) g_next[i] = atomicExch(&g_head[id], i);
    }
}

// ---------------------------------------------------------------------------
// scan beta sequentially (coalesced float4); scatter needed columns into g_ip
// ---------------------------------------------------------------------------
__global__ void scan_kernel(const float* __restrict__ beta) {
    const size_t gtid = (size_t)blockIdx.x * blockDim.x + threadIdx.x;
    const size_t stride = (size_t)gridDim.x * blockDim.x;
    const float4* b4 = reinterpret_cast<const float4*>(beta);
    const int4* h4 = reinterpret_cast<const int4*>(g_head);
    const size_t n4 = (size_t)H * V / 4;  // V%4==0
    for (size_t i = gtid; i < n4; i += stride) {
        int4 hd = __ldg(&h4[i % (V / 4)]);
        if ((hd.x | hd.y | hd.z | hd.w) >= 0 ||
            hd.x >= 0 || hd.y >= 0 || hd.z >= 0 || hd.w >= 0) {
            const int r = (int)(i / (V / 4));
            float4 v = __ldg(&b4[i]);
            int it = hd.x;
            while (it >= 0) {
                g_ip[(((size_t)(it >> 4)) * H + r) * B + (it & 15)] = v.x;
                it = g_next[it];
            }
            it = hd.y;
            while (it >= 0) {
                g_ip[(((size_t)(it >> 4)) * H + r) * B + (it & 15)] = v.y;
                it = g_next[it];
            }
            it = hd.z;
            while (it >= 0) {
                g_ip[(((size_t)(it >> 4)) * H + r) * B + (it & 15)] = v.z;
                it = g_next[it];
            }
            it = hd.w;
            while (it >= 0) {
                g_ip[(((size_t)(it >> 4)) * H + r) * B + (it & 15)] = v.w;
                it = g_next[it];
            }
        }
    }
}

// ---------------------------------------------------------------------------
// persistent kernel (R13 structure): flat flag barrier, tf32 MMA with alpha
// in register fragments, log/exp off the critical path, ip from g_ip
// ---------------------------------------------------------------------------
__global__ void __launch_bounds__(NTHR, 1) hmm_persist(
    const int* __restrict__ ids, const float* __restrict__ alpha,
    const float* __restrict__ gamma, float* __restrict__ out) {
    extern __shared__ float smem[];
    float* s_part = smem;                 // [256][PPAD] cross-warp partials
    float* s_misc = s_part + 256 * PPAD;  // [128] staging

    const int tid = threadIdx.x;
    const int blk = blockIdx.x;
    const int r0 = blk * 16;
    const int lane = tid & 31, w = tid >> 5;
    const int gid = lane >> 2;                 // MMA group id (0..7)
    const int tg = lane & 3;                   // thread-in-group (0..3)
    const int orow = tid >> 4, ob = tid & 15;  // epilogue mapping (tid<256)
    const bool epi = (tid < 256);
    const int kb = w * 128;                    // this warp's k slice

    __shared__ unsigned s_base;
    if (tid == 0) s_base = *(volatile unsigned*)&g_flag[blk];

    // preload alpha MMA A-fragments: rows {gid, gid+8}, cols {tg, tg+4} per ktile
    unsigned afr[16][4];
    #pragma unroll
    for (int kt = 0; kt < 16; kt++) {
        const int k0 = kb + kt * 8;
        afr[kt][0] = cvt_tf32(__ldg(&alpha[(size_t)(r0 + gid) * H + k0 + tg]));
        afr[kt][1] = cvt_tf32(__ldg(&alpha[(size_t)(r0 + gid + 8) * H + k0 + tg]));
        afr[kt][2] = cvt_tf32(__ldg(&alpha[(size_t)(r0 + gid) * H + k0 + tg + 4]));
        afr[kt][3] = cvt_tf32(__ldg(&alpha[(size_t)(r0 + gid + 8) * H + k0 + tg + 4]));
    }
    __syncthreads();
    const unsigned base = s_base;

    float m_prev = 0.f;  // shift used when E_{t-1} was published

    // ---- t = 0: y0 = ip[0] (already masked/zeroed); E_0 = tf32(exp(y0))
    {
        float y0 = 0.f;
        if (epi) {
            y0 = __ldg(&g_ip[((size_t)0 * H + r0 + orow) * B + ob]);
            g_E[0][(r0 + orow) * B + ob] = __uint_as_float(cvt_tf32(__expf(y0)));
            if (blk == 0 && tid < 16) g_shift[0][tid] = y0;
        }
        __syncthreads();
        if (tid == 0) atom_rel_exch(&g_flag[blk], base + 1u);
        if (epi) out[(size_t)(r0 + orow) * B + ob] = y0;
    }

    // ---- main recurrence
    for (int t = 1; t < S; t++) {
        const int par = (t - 1) & 1;

        // ip from pre-gathered buffer: 8 contiguous lines per block
        float ipv = 0.f;
        if (epi) ipv = __ldg(&g_ip[((size_t)t * H + r0 + orow) * B + ob]);

        // flat barrier: all blocks published step t-1
        if (tid < NBLK) {
            volatile unsigned* f = &g_flag[tid];
            const unsigned bt = base + (unsigned)t;
            while (*f < bt) {}
        }
        __syncthreads();

        // scale for publishing E_t, computed during the dot:
        // E_t = sum * exp(ip + m_prev - Mb)
        float Mb = 0.f, scale = 0.f;
        if (epi) {
            Mb = __ldcg(&g_shift[par][ob]);
            scale = __expf(ipv + m_prev - Mb);
        }

        // ---- tf32 MMA dot: D[16 x 16] over this warp's 128 k
        const float* Eg = g_E[par];
        float acc0[4] = {0.f, 0.f, 0.f, 0.f};  // cols 0..7
        float acc1[4] = {0.f, 0.f, 0.f, 0.f};  // cols 8..15
        #pragma unroll
        for (int kt = 0; kt < 16; kt++) {
            const int kr = kb + kt * 8 + tg;
            unsigned b0[2], b1[2];
            b0[0] = __float_as_uint(__ldcg(&Eg[kr * B + gid]));
            b0[1] = __float_as_uint(__ldcg(&Eg[(kr + 4) * B + gid]));
            b1[0] = __float_as_uint(__ldcg(&Eg[kr * B + 8 + gid]));
            b1[1] = __float_as_uint(__ldcg(&Eg[(kr + 4) * B + 8 + gid]));
            mma_tf32(acc0, afr[kt], b0, acc0);
            mma_tf32(acc1, afr[kt], b1, acc1);
        }

        // store partials: rows {gid, gid+8}, cols {2tg, 2tg+1} (+8 for acc1)
        s_part[(gid * 16 + 2 * tg) * PPAD + w] = acc0[0];
        s_part[(gid * 16 + 2 * tg + 1) * PPAD + w] = acc0[1];
        s_part[((gid + 8) * 16 + 2 * tg) * PPAD + w] = acc0[2];
        s_part[((gid + 8) * 16 + 2 * tg + 1) * PPAD + w] = acc0[3];
        s_part[(gid * 16 + 8 + 2 * tg) * PPAD + w] = acc1[0];
        s_part[(gid * 16 + 8 + 2 * tg + 1) * PPAD + w] = acc1[1];
        s_part[((gid + 8) * 16 + 8 + 2 * tg) * PPAD + w] = acc1[2];
        s_part[((gid + 8) * 16 + 8 + 2 * tg + 1) * PPAD + w] = acc1[3];
        __syncthreads();

        // fast epilogue: E_t = sum * scale (no log/exp on the chain)
        float sum = 0.f;
        if (epi) {
            const float* pp = s_part + tid * PPAD;
            #pragma unroll
            for (int c = 0; c < 16; c++) sum += pp[c];
            g_E[t & 1][(r0 + orow) * B + ob] =
                __uint_as_float(cvt_tf32(sum * scale));
            if (blk == 0 && tid < 16)
                g_shift[t & 1][tid] = __logf(sum) + m_prev + ipv;
            asm volatile("bar.sync 1, 256;" ::: "memory");
            if (tid == 0) atom_rel_exch(&g_flag[blk], base + (unsigned)(t + 1));
            // off the critical path:
            float y = __logf(sum) + m_prev + ipv;
            out[(size_t)t * H * B + (size_t)(r0 + orow) * B + ob] = y;
            m_prev = Mb;
        }
    }

    // ---- final fold: block b (<16): final[b] = log(sum_h softmax(gamma)_h *
    //      E_{S-1}[h,b]) + g_shift[(S-2)&1][b]
    if (blk < 16) {
        if (tid < NBLK) {
            volatile unsigned* f = &g_flag[tid];
            const unsigned bs = base + (unsigned)S;
            while (*f < bs) {}
        }
        __syncthreads();

        float gv[4];
        #pragma unroll
        for (int i = 0; i < 4; i++) gv[i] = __ldg(&gamma[tid + i * NTHR]);
        float gm = fmaxf(fmaxf(gv[0], gv[1]), fmaxf(gv[2], gv[3]));
        #pragma unroll
        for (int o = 16; o > 0; o >>= 1)
            gm = fmaxf(gm, __shfl_xor_sync(0xffffffffu, gm, o));
        if (lane == 0) s_misc[64 + w] = gm;
        __syncthreads();
        float gmax = s_misc[64];
        #pragma unroll
        for (int c = 1; c < 16; c++) gmax = fmaxf(gmax, s_misc[64 + c]);

        const float* El = g_E[(S - 1) & 1];
        float qs = 0.f, sm = 0.f;
        #pragma unroll
        for (int i = 0; i < 4; i++) {
            int h = tid + i * NTHR;
            float q = __expf(gv[i] - gmax);
            qs += q;
            sm += q * __ldcg(El + (size_t)h * B + blk);
        }
        #pragma unroll
        for (int o = 16; o > 0; o >>= 1) {
            qs += __shfl_xor_sync(0xffffffffu, qs, o);
            sm += __shfl_xor_sync(0xffffffffu, sm, o);
        }
        if (lane == 0) { s_misc[w] = qs; s_misc[32 + w] = sm; }
        __syncthreads();

        if (tid == 0) {
            float gsum = 0.f, tot = 0.f;
            #pragma unroll
            for (int c = 0; c < 16; c++) { gsum += s_misc[c]; tot += s_misc[32 + c]; }
            float shift = __ldcg(&g_shift[(S - 2) & 1][blk]);
            out[(size_t)S * H * B + blk] = __logf(tot) - __logf(gsum) + shift;
        }
    }
}

// ---------------------------------------------------------------------------
extern "C" void kernel_launch(void* const* d_in, const int* in_sizes, int n_in,
                              void* d_out, int out_size) {
    const int* ids = (const int*)d_in[0];        // (B, S) int32
    const float* alpha = (const float*)d_in[1];  // (H, H)
    const float* beta = (const float*)d_in[2];   // (H, V)
    const float* gamma = (const float*)d_in[3];  // (H,)
    float* out = (float*)d_out;                  // ys (S,H,B) then final (B,)

    const int smem_main = (256 * PPAD + 128) * (int)sizeof(float);
    cudaFuncSetAttribute(hmm_persist, cudaFuncAttributeMaxDynamicSharedMemorySize,
                         smem_main);

    prep_kernel<<<NBLK, NTHR>>>();
    build_kernel<<<(S * B + 255) / 256, 256>>>(ids);
    scan_kernel<<<NBLK, NTHR>>>(beta);
    hmm_persist<<<NBLK, NTHR, smem_main>>>(ids, alpha, gamma, out);
}